// round 3
// baseline (speedup 1.0000x reference)
#include <cuda_runtime.h>
#include <math.h>

#define Bn 16
#define Nn 256
#define Tn 64
#define Wn 12
#define Hn 64
#define EDn 64
#define Sn 5
#define Cn 4
#define En 2048
#define FGn 76   // W + H

// ---------------- device scratch (no allocation allowed) ----------------
__device__ float g_A[Nn * Nn];                 // static adjacency accumulator
__device__ float g_AnT[Nn * Nn];               // normalized static adj, transposed [j][i]
__device__ float g_dinv_stat[Nn];
__device__ float g_coef[6 * Hn];               // az, cz0, ar, cr0, ah, ch0
__device__ float g_XW[Bn * Nn * EDn];
__device__ float g_de1[Bn * Nn * EDn];
__device__ float g_de2[Bn * Nn * EDn];
__device__ float g_Eh[(size_t)Bn * Sn * Nn * Nn];   // ring buffer of Et
__device__ float g_Msum[(size_t)Bn * Nn * Nn];      // running sum over ring slots
__device__ float g_colsum[Bn * Nn];                 // column sums of Msum
__device__ float g_h[Bn * Nn * Hn];

// ---------------- setup kernels ----------------
__global__ void k_zero() {
    size_t idx = (size_t)blockIdx.x * blockDim.x + threadIdx.x;
    size_t str = (size_t)gridDim.x * blockDim.x;
    for (size_t i = idx; i < (size_t)Nn * Nn; i += str) g_A[i] = 0.f;
    for (size_t i = idx; i < (size_t)Bn * Sn * Nn * Nn; i += str) g_Eh[i] = 0.f;
    for (size_t i = idx; i < (size_t)Bn * Nn * Nn; i += str) g_Msum[i] = 0.f;
    for (size_t i = idx; i < (size_t)Bn * Nn; i += str) g_colsum[i] = 0.f;
    for (size_t i = idx; i < (size_t)Bn * Nn * Hn; i += str) g_h[i] = 0.f;
}

__global__ void k_scatter(const int* __restrict__ ei, const float* __restrict__ ew) {
    int e = blockIdx.x * blockDim.x + threadIdx.x;
    if (e < En) atomicAdd(&g_A[ei[e] * Nn + ei[En + e]], ew[e]);
}

__global__ void k_statdeg() {
    int j = threadIdx.x;  // 256 threads, 1 block
    float d = 1.0f;       // self loop
    for (int i = 0; i < Nn; i++) d += g_A[i * Nn + j];
    g_dinv_stat[j] = 1.0f / sqrtf(d);
}

__global__ void k_statAnT() {
    int idx = blockIdx.x * blockDim.x + threadIdx.x;
    if (idx >= Nn * Nn) return;
    int j = idx / Nn, i = idx % Nn;
    float a = g_A[i * Nn + j] + (i == j ? 1.0f : 0.0f);
    g_AnT[idx] = g_dinv_stat[i] * a * g_dinv_stat[j];
}

__global__ void k_precoef(const float* wz_c, const float* wz_l, const float* bz_c,
                          const float* wr_c, const float* wr_l, const float* br_c,
                          const float* wh_c, const float* wh_l, const float* bh_c) {
    int k = threadIdx.x;  // 64 threads
    float az = 0, cz = 0, ar = 0, cr = 0, ah = 0, ch = 0;
    for (int f = 0; f < Hn; f++) {
        float wzl = wz_l[f * Hn + k], wrl = wr_l[f * Hn + k], whl = wh_l[f * Hn + k];
        az += wz_c[f] * wzl;  cz += bz_c[f] * wzl;
        ar += wr_c[f] * wrl;  cr += br_c[f] * wrl;
        ah += wh_c[f] * whl;  ch += bh_c[f] * whl;
    }
    g_coef[k] = az;        g_coef[64 + k] = cz;
    g_coef[128 + k] = ar;  g_coef[192 + k] = cr;
    g_coef[256 + k] = ah;  g_coef[320 + k] = ch;
}

// ---------------- per-step kernel 1: XW = concat(win, h) @ Wg ----------------
__global__ __launch_bounds__(256) void k_xw(const float* __restrict__ x,
                                            const float* __restrict__ Wg, int t) {
    __shared__ float sW[FGn * EDn];     // 76*64
    __shared__ float sIt[16][FGn];
    int tid = threadIdx.x;
    for (int i = tid; i < FGn * EDn; i += 256) sW[i] = Wg[i];
    int row0 = blockIdx.x * 16;
    for (int i = tid; i < 16 * FGn; i += 256) {
        int rr = i / FGn, c = i % FGn;
        int row = row0 + rr;
        float v;
        if (c < Wn) {
            int tt = t + c - (Wn - 1);
            v = (tt >= 0) ? x[row * Tn + tt] : 0.0f;
        } else {
            v = g_h[row * Hn + (c - Wn)];
        }
        sIt[rr][c] = v;
    }
    __syncthreads();
    int f = tid & 63, r0 = tid >> 6;
#pragma unroll
    for (int q = 0; q < 4; q++) {
        int rr = r0 + q * 4;
        float acc = 0.f;
#pragma unroll
        for (int c = 0; c < FGn; c++) acc += sIt[rr][c] * sW[c * EDn + f];
        g_XW[(row0 + rr) * EDn + f] = acc;
    }
}

// -------- per-step kernel 2: df = AnT @ XW + b ; de1/de2 = tanh(df@W +b) --------
__global__ __launch_bounds__(256) void k_df_de(const float* __restrict__ gconv_b,
                                               const float* __restrict__ w1, const float* __restrict__ b1,
                                               const float* __restrict__ w2, const float* __restrict__ b2) {
    __shared__ float aT[32][33];
    __shared__ float xwS[32][64];
    __shared__ float dfS[32][64];
    __shared__ float wS[64 * 64];
    int b = blockIdx.y, jT = blockIdx.x;
    int tid = threadIdx.x;
    int f = tid & 63, jg = tid >> 6;  // jg in 0..3
    int j0 = jT * 32;
    float acc[8];
#pragma unroll
    for (int q = 0; q < 8; q++) acc[q] = 0.f;

    for (int ic = 0; ic < Nn; ic += 32) {
        for (int i = tid; i < 32 * 32; i += 256) {
            int jj = i >> 5, ii = i & 31;
            aT[jj][ii] = g_AnT[(j0 + jj) * Nn + ic + ii];
        }
        for (int i = tid; i < 32 * 64; i += 256) {
            int ii = i >> 6, ff = i & 63;
            xwS[ii][ff] = g_XW[(b * Nn + ic + ii) * EDn + ff];
        }
        __syncthreads();
#pragma unroll 4
        for (int ii = 0; ii < 32; ii++) {
            float xv = xwS[ii][f];
#pragma unroll
            for (int q = 0; q < 8; q++) acc[q] += aT[jg + q * 4][ii] * xv;
        }
        __syncthreads();
    }
    float gb = gconv_b[f];
#pragma unroll
    for (int q = 0; q < 8; q++) dfS[jg + q * 4][f] = acc[q] + gb;
    __syncthreads();

    // de1
    for (int i = tid; i < 4096; i += 256) wS[i] = w1[i];
    __syncthreads();
    {
        float bb = b1[f];
#pragma unroll
        for (int q = 0; q < 8; q++) {
            int jj = jg + q * 4;
            float a = bb;
#pragma unroll
            for (int ff = 0; ff < 64; ff++) a += dfS[jj][ff] * wS[ff * 64 + f];
            g_de1[(b * Nn + j0 + jj) * EDn + f] = tanhf(a);
        }
    }
    __syncthreads();
    // de2
    for (int i = tid; i < 4096; i += 256) wS[i] = w2[i];
    __syncthreads();
    {
        float bb = b2[f];
#pragma unroll
        for (int q = 0; q < 8; q++) {
            int jj = jg + q * 4;
            float a = bb;
#pragma unroll
            for (int ff = 0; ff < 64; ff++) a += dfS[jj][ff] * wS[ff * 64 + f];
            g_de2[(b * Nn + j0 + jj) * EDn + f] = tanhf(a);
        }
    }
}

// -------- per-step kernel 3: Et tiles + ring buffer + running sum + colsums --------
__global__ __launch_bounds__(256) void k_et(int slot) {
    __shared__ float d1i[32][65], d2i[32][65], d1j[32][65], d2j[32][65];
    __shared__ float tS[32][33];
    __shared__ float colbuf[64];
    int b = blockIdx.y;
    int tid = threadIdx.x;
    // decode triangular pair index -> (iT, jT), iT <= jT, 8 tiles per dim
    int p = blockIdx.x, iT = 0;
    while (p >= 8 - iT) { p -= 8 - iT; iT++; }
    int jT = iT + p;
    bool diag = (iT == jT);

    for (int i = tid; i < 32 * 64; i += 256) {
        int rr = i >> 6, e = i & 63;
        int gi = iT * 32 + rr, gj = jT * 32 + rr;
        d1i[rr][e] = g_de1[(b * Nn + gi) * EDn + e];
        d2i[rr][e] = g_de2[(b * Nn + gi) * EDn + e];
        d1j[rr][e] = g_de1[(b * Nn + gj) * EDn + e];
        d2j[rr][e] = g_de2[(b * Nn + gj) * EDn + e];
    }
    if (tid < 64) colbuf[tid] = 0.f;
    __syncthreads();

#pragma unroll
    for (int q = 0; q < 4; q++) {
        int idx = tid + q * 256;
        int ii = idx >> 5, jj = idx & 31;
        float a = 0.f, bb = 0.f;
#pragma unroll
        for (int e = 0; e < 64; e++) {
            a += d1i[ii][e] * d2j[jj][e];
            bb += d1j[jj][e] * d2i[ii][e];
        }
        tS[ii][jj] = tanhf(a - bb);
    }
    __syncthreads();

    // tile (iT, jT)
#pragma unroll
    for (int q = 0; q < 4; q++) {
        int idx = tid + q * 256;
        int ii = idx >> 5, jj = idx & 31;
        float et = fmaxf(tS[ii][jj], 0.f);
        int gi = iT * 32 + ii, gj = jT * 32 + jj;
        size_t eoff = (((size_t)(b * Sn + slot) * Nn + gi)) * Nn + gj;
        float old = g_Eh[eoff];
        g_Eh[eoff] = et;
        float delta = et - old;
        size_t moff = ((size_t)b * Nn + gi) * Nn + gj;
        g_Msum[moff] += delta;
        atomicAdd(&colbuf[jj], delta);
    }
    if (!diag) {
        // tile (jT, iT): row a in j-range, col c in i-range, value = relu(-t[c][a])
#pragma unroll
        for (int q = 0; q < 4; q++) {
            int idx = tid + q * 256;
            int a = idx >> 5, c = idx & 31;
            float et = fmaxf(-tS[c][a], 0.f);
            int gi = jT * 32 + a, gj = iT * 32 + c;
            size_t eoff = (((size_t)(b * Sn + slot) * Nn + gi)) * Nn + gj;
            float old = g_Eh[eoff];
            g_Eh[eoff] = et;
            float delta = et - old;
            size_t moff = ((size_t)b * Nn + gi) * Nn + gj;
            g_Msum[moff] += delta;
            atomicAdd(&colbuf[32 + c], delta);
        }
    }
    __syncthreads();
    if (tid < 32) atomicAdd(&g_colsum[b * Nn + jT * 32 + tid], colbuf[tid]);
    if (!diag && tid >= 32 && tid < 64)
        atomicAdd(&g_colsum[b * Nn + iT * 32 + (tid - 32)], colbuf[tid]);
}

// -------- per-step kernel 4: s-reduction + fused GRU update --------
__global__ __launch_bounds__(256) void k_gru(const float* __restrict__ x,
                                             const float* __restrict__ wz_l, const float* __restrict__ bz_l,
                                             const float* __restrict__ wr_l, const float* __restrict__ br_l,
                                             const float* __restrict__ wh_l, const float* __restrict__ bh_l,
                                             int t, float cnt) {
    __shared__ float dinvS[256];
    __shared__ float dxv[256];
    __shared__ float part[8][32];
    __shared__ float sS[32];
    __shared__ float hS[32][64];
    __shared__ float zS[32][64];
    __shared__ float hrS[32][64];
    __shared__ float wS[64 * 64];
    __shared__ float coefS[6 * 64];

    int b = blockIdx.y;
    int n0 = blockIdx.x * 32;
    int tid = threadIdx.x;
    float inv_cnt = 1.0f / cnt;

    {   // dinv and dinv*x for all 256 nodes of this batch
        int i = tid;
        float cs = g_colsum[b * Nn + i];
        float dv = 1.0f / sqrtf(cs * inv_cnt + 1.0f);
        dinvS[i] = dv;
        dxv[i] = dv * x[(b * Nn + i) * Tn + t];
    }
    __syncthreads();

    {   // partial column reductions of Msum over i for the 32 owned columns
        int c = tid & 31, g = tid >> 5;  // 8 groups of 32 i's
        float acc = 0.f;
        int ibase = g * 32;
#pragma unroll 8
        for (int k = 0; k < 32; k++) {
            int i = ibase + k;
            acc += g_Msum[((size_t)b * Nn + i) * Nn + n0 + c] * dxv[i];
        }
        part[g][c] = acc;
    }
    __syncthreads();
    if (tid < 32) {
        float sraw = 0.f;
#pragma unroll
        for (int g = 0; g < 8; g++) sraw += part[g][tid];
        int n = n0 + tid;
        float dj = dinvS[n];
        sS[tid] = dj * (sraw * inv_cnt + dj * x[(b * Nn + n) * Tn + t]);
    }
    for (int i = tid; i < 32 * 64; i += 256) {
        int rr = i >> 6, ff = i & 63;
        hS[rr][ff] = g_h[(b * Nn + n0 + rr) * Hn + ff];
    }
    for (int i = tid; i < 384; i += 256) coefS[i] = g_coef[i];
    __syncthreads();

    int k = tid & 63, rg = tid >> 6;  // 4 row groups; rows rg, rg+4, ..., rg+28

    // z = sigmoid(s*az + cz0 + h @ Wz2 + bz)
    for (int i = tid; i < 4096; i += 256) wS[i] = wz_l[(Hn + (i >> 6)) * Hn + (i & 63)];
    __syncthreads();
    {
        float bz = bz_l[k];
#pragma unroll
        for (int q = 0; q < 8; q++) {
            int rr = rg + q * 4;
            float a = sS[rr] * coefS[k] + coefS[64 + k] + bz;
#pragma unroll
            for (int ff = 0; ff < 64; ff++) a += hS[rr][ff] * wS[ff * 64 + k];
            zS[rr][k] = 1.0f / (1.0f + expf(-a));
        }
    }
    __syncthreads();
    // r -> hr = h * r
    for (int i = tid; i < 4096; i += 256) wS[i] = wr_l[(Hn + (i >> 6)) * Hn + (i & 63)];
    __syncthreads();
    {
        float br = br_l[k];
#pragma unroll
        for (int q = 0; q < 8; q++) {
            int rr = rg + q * 4;
            float a = sS[rr] * coefS[128 + k] + coefS[192 + k] + br;
#pragma unroll
            for (int ff = 0; ff < 64; ff++) a += hS[rr][ff] * wS[ff * 64 + k];
            float r = 1.0f / (1.0f + expf(-a));
            hrS[rr][k] = hS[rr][k] * r;
        }
    }
    __syncthreads();
    // ht = tanh(s*ah + ch0 + hr @ Wh2 + bh); h = z*h + (1-z)*ht
    for (int i = tid; i < 4096; i += 256) wS[i] = wh_l[(Hn + (i >> 6)) * Hn + (i & 63)];
    __syncthreads();
    {
        float bh = bh_l[k];
#pragma unroll
        for (int q = 0; q < 8; q++) {
            int rr = rg + q * 4;
            float a = sS[rr] * coefS[256 + k] + coefS[320 + k] + bh;
#pragma unroll
            for (int ff = 0; ff < 64; ff++) a += hrS[rr][ff] * wS[ff * 64 + k];
            float ht = tanhf(a);
            float z = zS[rr][k];
            g_h[(b * Nn + n0 + rr) * Hn + k] = z * hS[rr][k] + (1.0f - z) * ht;
        }
    }
}

// ---------------- final classifier ----------------
__global__ __launch_bounds__(256) void k_cls(const float* __restrict__ cls_w,
                                             const float* __restrict__ cls_b,
                                             float* __restrict__ out) {
    int b = blockIdx.x, tid = threadIdx.x;
    float acc[4] = {0.f, 0.f, 0.f, 0.f};
    for (int i = tid; i < Nn * Hn; i += 256) {
        float hv = g_h[b * Nn * Hn + i];
#pragma unroll
        for (int c = 0; c < 4; c++) acc[c] += hv * cls_w[i * Cn + c];
    }
    __shared__ float red[4][256];
#pragma unroll
    for (int c = 0; c < 4; c++) red[c][tid] = acc[c];
    __syncthreads();
    for (int s = 128; s > 0; s >>= 1) {
        if (tid < s) {
#pragma unroll
            for (int c = 0; c < 4; c++) red[c][tid] += red[c][tid + s];
        }
        __syncthreads();
    }
    if (tid < 4) out[b * Cn + tid] = red[tid][0] + cls_b[tid];
}

// ---------------- launch ----------------
extern "C" void kernel_launch(void* const* d_in, const int* in_sizes, int n_in,
                              void* d_out, int out_size) {
    const float* x        = (const float*)d_in[0];
    const float* ew       = (const float*)d_in[1];
    const float* gconv_w  = (const float*)d_in[2];
    const float* gconv_b  = (const float*)d_in[3];
    const float* w1       = (const float*)d_in[4];
    const float* b1       = (const float*)d_in[5];
    const float* w2       = (const float*)d_in[6];
    const float* b2       = (const float*)d_in[7];
    const float* wz_c     = (const float*)d_in[8];
    const float* bz_c     = (const float*)d_in[9];
    const float* wz_l     = (const float*)d_in[10];
    const float* bz_l     = (const float*)d_in[11];
    const float* wr_c     = (const float*)d_in[12];
    const float* br_c     = (const float*)d_in[13];
    const float* wr_l     = (const float*)d_in[14];
    const float* br_l     = (const float*)d_in[15];
    const float* wh_c     = (const float*)d_in[16];
    const float* bh_c     = (const float*)d_in[17];
    const float* wh_l     = (const float*)d_in[18];
    const float* bh_l     = (const float*)d_in[19];
    const float* cls_w    = (const float*)d_in[20];
    const float* cls_b    = (const float*)d_in[21];
    const int*   eidx     = (const int*)d_in[22];
    float* out = (float*)d_out;

    k_zero<<<2048, 256>>>();
    k_scatter<<<(En + 255) / 256, 256>>>(eidx, ew);
    k_statdeg<<<1, 256>>>();
    k_statAnT<<<(Nn * Nn + 255) / 256, 256>>>();
    k_precoef<<<1, 64>>>(wz_c, wz_l, bz_c, wr_c, wr_l, br_c, wh_c, wh_l, bh_c);

    for (int t = 0; t < Tn; t++) {
        int slot = t % Sn;
        float cnt = (float)((t + 1 < Sn) ? (t + 1) : Sn);
        k_xw<<<Bn * Nn / 16, 256>>>(x, gconv_w, t);
        k_df_de<<<dim3(8, Bn), 256>>>(gconv_b, w1, b1, w2, b2);
        k_et<<<dim3(36, Bn), 256>>>(slot);
        k_gru<<<dim3(8, Bn), 256>>>(x, wz_l, bz_l, wr_l, br_l, wh_l, bh_l, t, cnt);
    }

    k_cls<<<Bn, 256>>>(cls_w, cls_b, out);
}

// round 4
// speedup vs baseline: 1.0016x; 1.0016x over previous
#include <cuda_runtime.h>
#include <math.h>

#define Bn 16
#define Nn 256
#define Tn 64
#define Wn 12
#define Hn 64
#define EDn 64
#define Sn 5
#define Cn 4
#define En 2048
#define FGn 76   // W + H

// ---------------- device scratch (no allocation allowed) ----------------
__device__ float g_A[Nn * Nn];                 // static adjacency accumulator
__device__ float g_AnT[Nn * Nn];               // normalized static adj, transposed [j][i]
__device__ float g_dinv_stat[Nn];
__device__ float g_coef[6 * Hn];               // az, cz0, ar, cr0, ah, ch0
__device__ float g_XW[Bn * Nn * EDn];
__device__ float g_de1[Bn * Nn * EDn];
__device__ float g_de2[Bn * Nn * EDn];
__device__ float g_Eh[(size_t)Bn * Sn * Nn * Nn];   // ring buffer of Et
__device__ float g_Msum[(size_t)Bn * Nn * Nn];      // running sum over ring slots
__device__ float g_colsum[Bn * Nn];                 // column sums of Msum
__device__ float g_h[Bn * Nn * Hn];

// ---------------- setup kernels ----------------
__global__ void k_zero() {
    size_t idx = (size_t)blockIdx.x * blockDim.x + threadIdx.x;
    size_t str = (size_t)gridDim.x * blockDim.x;
    for (size_t i = idx; i < (size_t)Nn * Nn; i += str) g_A[i] = 0.f;
    for (size_t i = idx; i < (size_t)Bn * Sn * Nn * Nn; i += str) g_Eh[i] = 0.f;
    for (size_t i = idx; i < (size_t)Bn * Nn * Nn; i += str) g_Msum[i] = 0.f;
    for (size_t i = idx; i < (size_t)Bn * Nn; i += str) g_colsum[i] = 0.f;
    for (size_t i = idx; i < (size_t)Bn * Nn * Hn; i += str) g_h[i] = 0.f;
}

__global__ void k_scatter(const int* __restrict__ ei, const float* __restrict__ ew) {
    int e = blockIdx.x * blockDim.x + threadIdx.x;
    if (e < En) atomicAdd(&g_A[ei[e] * Nn + ei[En + e]], ew[e]);
}

__global__ void k_statdeg() {
    int j = threadIdx.x;  // 256 threads, 1 block
    float d = 1.0f;       // self loop
    for (int i = 0; i < Nn; i++) d += g_A[i * Nn + j];
    g_dinv_stat[j] = 1.0f / sqrtf(d);
}

__global__ void k_statAnT() {
    int idx = blockIdx.x * blockDim.x + threadIdx.x;
    if (idx >= Nn * Nn) return;
    int j = idx / Nn, i = idx % Nn;
    float a = g_A[i * Nn + j] + (i == j ? 1.0f : 0.0f);
    g_AnT[idx] = g_dinv_stat[i] * a * g_dinv_stat[j];
}

__global__ void k_precoef(const float* wz_c, const float* wz_l, const float* bz_c,
                          const float* wr_c, const float* wr_l, const float* br_c,
                          const float* wh_c, const float* wh_l, const float* bh_c) {
    int k = threadIdx.x;  // 64 threads
    float az = 0, cz = 0, ar = 0, cr = 0, ah = 0, ch = 0;
    for (int f = 0; f < Hn; f++) {
        float wzl = wz_l[f * Hn + k], wrl = wr_l[f * Hn + k], whl = wh_l[f * Hn + k];
        az += wz_c[f] * wzl;  cz += bz_c[f] * wzl;
        ar += wr_c[f] * wrl;  cr += br_c[f] * wrl;
        ah += wh_c[f] * whl;  ch += bh_c[f] * whl;
    }
    g_coef[k] = az;        g_coef[64 + k] = cz;
    g_coef[128 + k] = ar;  g_coef[192 + k] = cr;
    g_coef[256 + k] = ah;  g_coef[320 + k] = ch;
}

// ---------------- per-step kernel 1: XW = concat(win, h) @ Wg ----------------
__global__ __launch_bounds__(256) void k_xw(const float* __restrict__ x,
                                            const float* __restrict__ Wg, int t) {
    __shared__ float sW[FGn * EDn];     // 76*64
    __shared__ float sIt[16][FGn];
    int tid = threadIdx.x;
    for (int i = tid; i < FGn * EDn; i += 256) sW[i] = Wg[i];
    int row0 = blockIdx.x * 16;
    for (int i = tid; i < 16 * FGn; i += 256) {
        int rr = i / FGn, c = i % FGn;
        int row = row0 + rr;
        float v;
        if (c < Wn) {
            int tt = t + c - (Wn - 1);
            v = (tt >= 0) ? x[row * Tn + tt] : 0.0f;
        } else {
            v = g_h[row * Hn + (c - Wn)];
        }
        sIt[rr][c] = v;
    }
    __syncthreads();
    int f = tid & 63, r0 = tid >> 6;
#pragma unroll
    for (int q = 0; q < 4; q++) {
        int rr = r0 + q * 4;
        float acc = 0.f;
#pragma unroll
        for (int c = 0; c < FGn; c++) acc += sIt[rr][c] * sW[c * EDn + f];
        g_XW[(row0 + rr) * EDn + f] = acc;
    }
}

// -------- per-step kernel 2: df = AnT @ XW + b ; de1/de2 = tanh(df@W +b) --------
__global__ __launch_bounds__(256) void k_df_de(const float* __restrict__ gconv_b,
                                               const float* __restrict__ w1, const float* __restrict__ b1,
                                               const float* __restrict__ w2, const float* __restrict__ b2) {
    __shared__ float aT[32][33];
    __shared__ float xwS[32][64];
    __shared__ float dfS[32][64];
    __shared__ float wS[64 * 64];
    int b = blockIdx.y, jT = blockIdx.x;
    int tid = threadIdx.x;
    int f = tid & 63, jg = tid >> 6;  // jg in 0..3
    int j0 = jT * 32;
    float acc[8];
#pragma unroll
    for (int q = 0; q < 8; q++) acc[q] = 0.f;

    for (int ic = 0; ic < Nn; ic += 32) {
        for (int i = tid; i < 32 * 32; i += 256) {
            int jj = i >> 5, ii = i & 31;
            aT[jj][ii] = g_AnT[(j0 + jj) * Nn + ic + ii];
        }
        for (int i = tid; i < 32 * 64; i += 256) {
            int ii = i >> 6, ff = i & 63;
            xwS[ii][ff] = g_XW[(b * Nn + ic + ii) * EDn + ff];
        }
        __syncthreads();
#pragma unroll 4
        for (int ii = 0; ii < 32; ii++) {
            float xv = xwS[ii][f];
#pragma unroll
            for (int q = 0; q < 8; q++) acc[q] += aT[jg + q * 4][ii] * xv;
        }
        __syncthreads();
    }
    float gb = gconv_b[f];
#pragma unroll
    for (int q = 0; q < 8; q++) dfS[jg + q * 4][f] = acc[q] + gb;
    __syncthreads();

    // de1
    for (int i = tid; i < 4096; i += 256) wS[i] = w1[i];
    __syncthreads();
    {
        float bb = b1[f];
#pragma unroll
        for (int q = 0; q < 8; q++) {
            int jj = jg + q * 4;
            float a = bb;
#pragma unroll
            for (int ff = 0; ff < 64; ff++) a += dfS[jj][ff] * wS[ff * 64 + f];
            g_de1[(b * Nn + j0 + jj) * EDn + f] = tanhf(a);
        }
    }
    __syncthreads();
    // de2
    for (int i = tid; i < 4096; i += 256) wS[i] = w2[i];
    __syncthreads();
    {
        float bb = b2[f];
#pragma unroll
        for (int q = 0; q < 8; q++) {
            int jj = jg + q * 4;
            float a = bb;
#pragma unroll
            for (int ff = 0; ff < 64; ff++) a += dfS[jj][ff] * wS[ff * 64 + f];
            g_de2[(b * Nn + j0 + jj) * EDn + f] = tanhf(a);
        }
    }
}

// -------- per-step kernel 3: Et tiles + ring buffer + running sum + colsums --------
__global__ __launch_bounds__(256) void k_et(int slot) {
    __shared__ float d1i[32][65], d2i[32][65], d1j[32][65], d2j[32][65];
    __shared__ float tS[32][33];
    __shared__ float colbuf[64];
    int b = blockIdx.y;
    int tid = threadIdx.x;
    // decode triangular pair index -> (iT, jT), iT <= jT, 8 tiles per dim
    int p = blockIdx.x, iT = 0;
    while (p >= 8 - iT) { p -= 8 - iT; iT++; }
    int jT = iT + p;
    bool diag = (iT == jT);

    for (int i = tid; i < 32 * 64; i += 256) {
        int rr = i >> 6, e = i & 63;
        int gi = iT * 32 + rr, gj = jT * 32 + rr;
        d1i[rr][e] = g_de1[(b * Nn + gi) * EDn + e];
        d2i[rr][e] = g_de2[(b * Nn + gi) * EDn + e];
        d1j[rr][e] = g_de1[(b * Nn + gj) * EDn + e];
        d2j[rr][e] = g_de2[(b * Nn + gj) * EDn + e];
    }
    if (tid < 64) colbuf[tid] = 0.f;
    __syncthreads();

#pragma unroll
    for (int q = 0; q < 4; q++) {
        int idx = tid + q * 256;
        int ii = idx >> 5, jj = idx & 31;
        float a = 0.f, bb = 0.f;
#pragma unroll
        for (int e = 0; e < 64; e++) {
            a += d1i[ii][e] * d2j[jj][e];
            bb += d1j[jj][e] * d2i[ii][e];
        }
        tS[ii][jj] = tanhf(a - bb);
    }
    __syncthreads();

    // tile (iT, jT)
#pragma unroll
    for (int q = 0; q < 4; q++) {
        int idx = tid + q * 256;
        int ii = idx >> 5, jj = idx & 31;
        float et = fmaxf(tS[ii][jj], 0.f);
        int gi = iT * 32 + ii, gj = jT * 32 + jj;
        size_t eoff = (((size_t)(b * Sn + slot) * Nn + gi)) * Nn + gj;
        float old = g_Eh[eoff];
        g_Eh[eoff] = et;
        float delta = et - old;
        size_t moff = ((size_t)b * Nn + gi) * Nn + gj;
        g_Msum[moff] += delta;
        atomicAdd(&colbuf[jj], delta);
    }
    if (!diag) {
        // tile (jT, iT): row a in j-range, col c in i-range, value = relu(-t[c][a])
#pragma unroll
        for (int q = 0; q < 4; q++) {
            int idx = tid + q * 256;
            int a = idx >> 5, c = idx & 31;
            float et = fmaxf(-tS[c][a], 0.f);
            int gi = jT * 32 + a, gj = iT * 32 + c;
            size_t eoff = (((size_t)(b * Sn + slot) * Nn + gi)) * Nn + gj;
            float old = g_Eh[eoff];
            g_Eh[eoff] = et;
            float delta = et - old;
            size_t moff = ((size_t)b * Nn + gi) * Nn + gj;
            g_Msum[moff] += delta;
            atomicAdd(&colbuf[32 + c], delta);
        }
    }
    __syncthreads();
    if (tid < 32) atomicAdd(&g_colsum[b * Nn + jT * 32 + tid], colbuf[tid]);
    if (!diag && tid >= 32 && tid < 64)
        atomicAdd(&g_colsum[b * Nn + iT * 32 + (tid - 32)], colbuf[tid]);
}

// -------- per-step kernel 4: s-reduction + fused GRU update --------
__global__ __launch_bounds__(256) void k_gru(const float* __restrict__ x,
                                             const float* __restrict__ wz_l, const float* __restrict__ bz_l,
                                             const float* __restrict__ wr_l, const float* __restrict__ br_l,
                                             const float* __restrict__ wh_l, const float* __restrict__ bh_l,
                                             int t, float cnt) {
    __shared__ float dinvS[256];
    __shared__ float dxv[256];
    __shared__ float part[8][32];
    __shared__ float sS[32];
    __shared__ float hS[32][64];
    __shared__ float zS[32][64];
    __shared__ float hrS[32][64];
    __shared__ float wS[64 * 64];
    __shared__ float coefS[6 * 64];

    int b = blockIdx.y;
    int n0 = blockIdx.x * 32;
    int tid = threadIdx.x;
    float inv_cnt = 1.0f / cnt;

    {   // dinv and dinv*x for all 256 nodes of this batch
        int i = tid;
        float cs = g_colsum[b * Nn + i];
        float dv = 1.0f / sqrtf(cs * inv_cnt + 1.0f);
        dinvS[i] = dv;
        dxv[i] = dv * x[(b * Nn + i) * Tn + t];
    }
    __syncthreads();

    {   // partial column reductions of Msum over i for the 32 owned columns
        int c = tid & 31, g = tid >> 5;  // 8 groups of 32 i's
        float acc = 0.f;
        int ibase = g * 32;
#pragma unroll 8
        for (int k = 0; k < 32; k++) {
            int i = ibase + k;
            acc += g_Msum[((size_t)b * Nn + i) * Nn + n0 + c] * dxv[i];
        }
        part[g][c] = acc;
    }
    __syncthreads();
    if (tid < 32) {
        float sraw = 0.f;
#pragma unroll
        for (int g = 0; g < 8; g++) sraw += part[g][tid];
        int n = n0 + tid;
        float dj = dinvS[n];
        sS[tid] = dj * (sraw * inv_cnt + dj * x[(b * Nn + n) * Tn + t]);
    }
    for (int i = tid; i < 32 * 64; i += 256) {
        int rr = i >> 6, ff = i & 63;
        hS[rr][ff] = g_h[(b * Nn + n0 + rr) * Hn + ff];
    }
    for (int i = tid; i < 384; i += 256) coefS[i] = g_coef[i];
    __syncthreads();

    int k = tid & 63, rg = tid >> 6;  // 4 row groups; rows rg, rg+4, ..., rg+28

    // z = sigmoid(s*az + cz0 + h @ Wz2 + bz)
    for (int i = tid; i < 4096; i += 256) wS[i] = wz_l[(Hn + (i >> 6)) * Hn + (i & 63)];
    __syncthreads();
    {
        float bz = bz_l[k];
#pragma unroll
        for (int q = 0; q < 8; q++) {
            int rr = rg + q * 4;
            float a = sS[rr] * coefS[k] + coefS[64 + k] + bz;
#pragma unroll
            for (int ff = 0; ff < 64; ff++) a += hS[rr][ff] * wS[ff * 64 + k];
            zS[rr][k] = 1.0f / (1.0f + expf(-a));
        }
    }
    __syncthreads();
    // r -> hr = h * r
    for (int i = tid; i < 4096; i += 256) wS[i] = wr_l[(Hn + (i >> 6)) * Hn + (i & 63)];
    __syncthreads();
    {
        float br = br_l[k];
#pragma unroll
        for (int q = 0; q < 8; q++) {
            int rr = rg + q * 4;
            float a = sS[rr] * coefS[128 + k] + coefS[192 + k] + br;
#pragma unroll
            for (int ff = 0; ff < 64; ff++) a += hS[rr][ff] * wS[ff * 64 + k];
            float r = 1.0f / (1.0f + expf(-a));
            hrS[rr][k] = hS[rr][k] * r;
        }
    }
    __syncthreads();
    // ht = tanh(s*ah + ch0 + hr @ Wh2 + bh); h = z*h + (1-z)*ht
    for (int i = tid; i < 4096; i += 256) wS[i] = wh_l[(Hn + (i >> 6)) * Hn + (i & 63)];
    __syncthreads();
    {
        float bh = bh_l[k];
#pragma unroll
        for (int q = 0; q < 8; q++) {
            int rr = rg + q * 4;
            float a = sS[rr] * coefS[256 + k] + coefS[320 + k] + bh;
#pragma unroll
            for (int ff = 0; ff < 64; ff++) a += hrS[rr][ff] * wS[ff * 64 + k];
            float ht = tanhf(a);
            float z = zS[rr][k];
            g_h[(b * Nn + n0 + rr) * Hn + k] = z * hS[rr][k] + (1.0f - z) * ht;
        }
    }
}

// ---------------- final classifier ----------------
__global__ __launch_bounds__(256) void k_cls(const float* __restrict__ cls_w,
                                             const float* __restrict__ cls_b,
                                             float* __restrict__ out) {
    int b = blockIdx.x, tid = threadIdx.x;
    float acc[4] = {0.f, 0.f, 0.f, 0.f};
    for (int i = tid; i < Nn * Hn; i += 256) {
        float hv = g_h[b * Nn * Hn + i];
#pragma unroll
        for (int c = 0; c < 4; c++) acc[c] += hv * cls_w[i * Cn + c];
    }
    __shared__ float red[4][256];
#pragma unroll
    for (int c = 0; c < 4; c++) red[c][tid] = acc[c];
    __syncthreads();
    for (int s = 128; s > 0; s >>= 1) {
        if (tid < s) {
#pragma unroll
            for (int c = 0; c < 4; c++) red[c][tid] += red[c][tid + s];
        }
        __syncthreads();
    }
    if (tid < 4) out[b * Cn + tid] = red[tid][0] + cls_b[tid];
}

// ---------------- launch ----------------
extern "C" void kernel_launch(void* const* d_in, const int* in_sizes, int n_in,
                              void* d_out, int out_size) {
    const float* x        = (const float*)d_in[0];
    const float* ew       = (const float*)d_in[1];
    const float* gconv_w  = (const float*)d_in[2];
    const float* gconv_b  = (const float*)d_in[3];
    const float* w1       = (const float*)d_in[4];
    const float* b1       = (const float*)d_in[5];
    const float* w2       = (const float*)d_in[6];
    const float* b2       = (const float*)d_in[7];
    const float* wz_c     = (const float*)d_in[8];
    const float* bz_c     = (const float*)d_in[9];
    const float* wz_l     = (const float*)d_in[10];
    const float* bz_l     = (const float*)d_in[11];
    const float* wr_c     = (const float*)d_in[12];
    const float* br_c     = (const float*)d_in[13];
    const float* wr_l     = (const float*)d_in[14];
    const float* br_l     = (const float*)d_in[15];
    const float* wh_c     = (const float*)d_in[16];
    const float* bh_c     = (const float*)d_in[17];
    const float* wh_l     = (const float*)d_in[18];
    const float* bh_l     = (const float*)d_in[19];
    const float* cls_w    = (const float*)d_in[20];
    const float* cls_b    = (const float*)d_in[21];
    const int*   eidx     = (const int*)d_in[22];
    float* out = (float*)d_out;

    k_zero<<<2048, 256>>>();
    k_scatter<<<(En + 255) / 256, 256>>>(eidx, ew);
    k_statdeg<<<1, 256>>>();
    k_statAnT<<<(Nn * Nn + 255) / 256, 256>>>();
    k_precoef<<<1, 64>>>(wz_c, wz_l, bz_c, wr_c, wr_l, br_c, wh_c, wh_l, bh_c);

    for (int t = 0; t < Tn; t++) {
        int slot = t % Sn;
        float cnt = (float)((t + 1 < Sn) ? (t + 1) : Sn);
        k_xw<<<Bn * Nn / 16, 256>>>(x, gconv_w, t);
        k_df_de<<<dim3(8, Bn), 256>>>(gconv_b, w1, b1, w2, b2);
        k_et<<<dim3(36, Bn), 256>>>(slot);
        k_gru<<<dim3(8, Bn), 256>>>(x, wz_l, bz_l, wr_l, br_l, wh_l, bh_l, t, cnt);
    }

    k_cls<<<Bn, 256>>>(cls_w, cls_b, out);
}